// round 5
// baseline (speedup 1.0000x reference)
#include <cuda_runtime.h>
#include <cuda_bf16.h>
#include <cstdint>

// ============================================================================
// S4D: K[i] = C @ A^i @ B, A diagonal.
//   K[i][m][d] = sum_n C[m][n] * a_n^i * B[n][d]
//   => GEMM: K[4096, 16384] = V[4096, 64] @ W[64, 16384]
// sm_103 generic target -> mma.sync bf16 (HMMA), bf16x3 split
// (hi*hi + hi*lo + lo*hi), operands pre-stored in fragment order (no SMEM).
// R5: 2 N-subtiles per CTA + cross-subtile fragment prefetch.
// ============================================================================

#define L_LEN 4096
#define NS 64
#define DM 128
#define COLS_TOTAL (DM * DM)   // 16384

// A-fragment array: [blkf(256)][ks(4)][lane(32)] uint4; rows r0=blkf*16+lane/4
#define VF_ELEMS (256 * 4 * 32)          // 32768
// B-fragment array: [nbf(2048)][ks(4)][lane(32)] uint2; col=nbf*8+lane/4
#define WF_ELEMS (2048 * 4 * 32)         // 262144

__device__ uint4 g_VFhi[VF_ELEMS];
__device__ uint4 g_VFlo[VF_ELEMS];
__device__ uint2 g_WFhi[WF_ELEMS];
__device__ uint2 g_WFlo[WF_ELEMS];

__device__ __forceinline__ void mma_16816(float* c, const uint32_t* a,
                                          const uint32_t* b) {
    asm volatile(
        "mma.sync.aligned.m16n8k16.row.col.f32.bf16.bf16.f32 "
        "{%0,%1,%2,%3}, {%4,%5,%6,%7}, {%8,%9}, {%0,%1,%2,%3};"
        : "+f"(c[0]), "+f"(c[1]), "+f"(c[2]), "+f"(c[3])
        : "r"(a[0]), "r"(a[1]), "r"(a[2]), "r"(a[3]), "r"(b[0]), "r"(b[1]));
}

__device__ __forceinline__ uint32_t pack_bf2(__nv_bfloat16 x, __nv_bfloat16 y) {
    __nv_bfloat162 t(x, y);
    return *(uint32_t*)&t;
}

__device__ __forceinline__ void split2(float v0, float v1,
                                       uint32_t& hi, uint32_t& lo) {
    __nv_bfloat16 h0 = __float2bfloat16(v0);
    __nv_bfloat16 h1 = __float2bfloat16(v1);
    float l0 = v0 - __bfloat162float(h0);
    float l1 = v1 - __bfloat162float(h1);
    hi = pack_bf2(h0, h1);
    lo = pack_bf2(__float2bfloat16(l0), __float2bfloat16(l1));
}

// v(i,n) = a_n^i = 2^(i*l2a) : one fp64 mul + exp2f + ldexpf
__device__ __forceinline__ float pow_in(int i, double l2) {
    double e = (double)i * l2;
    if (e < -200.0) return 0.0f;
    double fl = floor(e);
    return ldexpf(exp2f((float)(e - fl)), (int)fl);
}

// ============================================================================
// Prep 1: V in A-fragment order (log2 computed block-locally in fp64).
// ============================================================================
__global__ void s4d_prep_vf(const float* __restrict__ A) {
    __shared__ double s_l2a[NS];
    if (threadIdx.x < NS) {
        float a = A[threadIdx.x * NS + threadIdx.x];
        s_l2a[threadIdx.x] = (a > 0.0f) ? log2((double)a) : -1.0e30;
    }
    __syncthreads();

    int idx = blockIdx.x * blockDim.x + threadIdx.x;
    if (idx >= VF_ELEMS) return;
    int lane = idx & 31;
    int ks   = (idx >> 5) & 3;
    int blkf = idx >> 7;
    int g  = lane >> 2;
    int tg = lane & 3;
    int r0 = blkf * 16 + g;
    int r1 = r0 + 8;
    int k0 = ks * 16 + tg * 2;

    double l2_0 = s_l2a[k0],     l2_1 = s_l2a[k0 + 1];
    double l2_8 = s_l2a[k0 + 8], l2_9 = s_l2a[k0 + 9];

    uint4 hi, lo;
    split2(pow_in(r0, l2_0), pow_in(r0, l2_1), hi.x, lo.x);
    split2(pow_in(r1, l2_0), pow_in(r1, l2_1), hi.y, lo.y);
    split2(pow_in(r0, l2_8), pow_in(r0, l2_9), hi.z, lo.z);
    split2(pow_in(r1, l2_8), pow_in(r1, l2_9), hi.w, lo.w);
    g_VFhi[idx] = hi;
    g_VFlo[idx] = lo;
}

// ============================================================================
// Prep 2: W[col][n] = C[m][n]*B[n][d] in B-fragment order.
// ============================================================================
__global__ void s4d_prep_wf(const float* __restrict__ C, const float* __restrict__ Bm) {
    int idx = blockIdx.x * blockDim.x + threadIdx.x;
    if (idx >= WF_ELEMS) return;
    int lane = idx & 31;
    int ks   = (idx >> 5) & 3;
    int nbf  = idx >> 7;
    int g  = lane >> 2;
    int tg = lane & 3;
    int col = nbf * 8 + g;
    int k0  = ks * 16 + tg * 2;
    int m = col >> 7;
    int d = col & 127;

    const float* Crow = C + m * NS;
    float w0 = Crow[k0]     * Bm[k0 * DM + d];
    float w1 = Crow[k0 + 1] * Bm[(k0 + 1) * DM + d];
    float w8 = Crow[k0 + 8] * Bm[(k0 + 8) * DM + d];
    float w9 = Crow[k0 + 9] * Bm[(k0 + 9) * DM + d];

    uint2 hi, lo;
    split2(w0, w1, hi.x, lo.x);
    split2(w8, w9, hi.y, lo.y);
    g_WFhi[idx] = hi;
    g_WFlo[idx] = lo;
}

// ============================================================================
// Main: CTA region = 128 rows x 256 cols, two 128x128 subtiles.
// 8 warps of 64x32. Fragment-order LDG, no SMEM. Cross-subtile prefetch:
// subtile1's ks=0 fragments load before subtile0's epilogue stores.
// ============================================================================
__global__ void __launch_bounds__(256, 2) s4d_mma_kernel(float* __restrict__ out) {
    const int tid  = threadIdx.x;
    const int wid  = tid >> 5;
    const int lane = tid & 31;
    const int m_w = (wid & 1) * 64;
    const int n_w = (wid >> 1) * 32;

    // A base: ((by*8 + m_w/16 + mi)*4 + ks)*32 + lane
    const int abase = (blockIdx.y * 8 + (m_w >> 4)) * 128 + lane;
    // B base for subtile s: ((bx*32 + s*16 + n_w/8 + ni)*4 + ks)*32 + lane
    const int bbase0 = (blockIdx.x * 32 + (n_w >> 3)) * 128 + lane;

    const int gm = blockIdx.y * 128 + m_w + (lane >> 2);
    const int gn0 = blockIdx.x * 256 + n_w + (lane & 3) * 2;

    // prefetched ks=0 fragments for the upcoming subtile
    uint4 pahi[4];
    uint2 pbhi[4], pblo[4];
#pragma unroll
    for (int mi = 0; mi < 4; mi++) pahi[mi] = g_VFhi[abase + mi * 128];
#pragma unroll
    for (int ni = 0; ni < 4; ni++) pbhi[ni] = g_WFhi[bbase0 + ni * 128];
#pragma unroll
    for (int ni = 0; ni < 4; ni++) pblo[ni] = g_WFlo[bbase0 + ni * 128];

#pragma unroll
    for (int s = 0; s < 2; s++) {
        const int bbase = bbase0 + s * (16 * 128);

        float c[4][4][4];
#pragma unroll
        for (int mi = 0; mi < 4; mi++)
#pragma unroll
            for (int ni = 0; ni < 4; ni++)
#pragma unroll
                for (int k = 0; k < 4; k++) c[mi][ni][k] = 0.0f;

#pragma unroll
        for (int ks = 0; ks < 4; ks++) {
            uint4 ahi[4];
            uint2 bhi[4], blo[4];
            if (ks == 0) {
#pragma unroll
                for (int mi = 0; mi < 4; mi++) ahi[mi] = pahi[mi];
#pragma unroll
                for (int ni = 0; ni < 4; ni++) { bhi[ni] = pbhi[ni]; blo[ni] = pblo[ni]; }
            } else {
#pragma unroll
                for (int mi = 0; mi < 4; mi++) ahi[mi] = g_VFhi[abase + mi * 128 + ks * 32];
#pragma unroll
                for (int ni = 0; ni < 4; ni++) bhi[ni] = g_WFhi[bbase + ni * 128 + ks * 32];
#pragma unroll
                for (int ni = 0; ni < 4; ni++) blo[ni] = g_WFlo[bbase + ni * 128 + ks * 32];
            }

#pragma unroll
            for (int mi = 0; mi < 4; mi++)
#pragma unroll
                for (int ni = 0; ni < 4; ni++)
                    mma_16816(c[mi][ni], (const uint32_t*)&ahi[mi],
                              (const uint32_t*)&bhi[ni]);
#pragma unroll
            for (int mi = 0; mi < 4; mi++)
#pragma unroll
                for (int ni = 0; ni < 4; ni++)
                    mma_16816(c[mi][ni], (const uint32_t*)&ahi[mi],
                              (const uint32_t*)&blo[ni]);

            uint4 alo[4];
#pragma unroll
            for (int mi = 0; mi < 4; mi++) alo[mi] = g_VFlo[abase + mi * 128 + ks * 32];
#pragma unroll
            for (int mi = 0; mi < 4; mi++)
#pragma unroll
                for (int ni = 0; ni < 4; ni++)
                    mma_16816(c[mi][ni], (const uint32_t*)&alo[mi],
                              (const uint32_t*)&bhi[ni]);
        }

        // prefetch next subtile's ks=0 fragments before the stores
        if (s == 0) {
            const int bb1 = bbase0 + 16 * 128;
#pragma unroll
            for (int mi = 0; mi < 4; mi++) pahi[mi] = g_VFhi[abase + mi * 128];
#pragma unroll
            for (int ni = 0; ni < 4; ni++) pbhi[ni] = g_WFhi[bb1 + ni * 128];
#pragma unroll
            for (int ni = 0; ni < 4; ni++) pblo[ni] = g_WFlo[bb1 + ni * 128];
        }

        // epilogue: fragment-direct float2 stores (full 32B sectors)
        const int gn = gn0 + s * 128;
#pragma unroll
        for (int mi = 0; mi < 4; mi++) {
            size_t r0 = (size_t)(gm + mi * 16) * COLS_TOTAL + gn;
            size_t r1 = r0 + (size_t)8 * COLS_TOTAL;
#pragma unroll
            for (int ni = 0; ni < 4; ni++) {
                *(float2*)(out + r0 + ni * 8) = make_float2(c[mi][ni][0], c[mi][ni][1]);
                *(float2*)(out + r1 + ni * 8) = make_float2(c[mi][ni][2], c[mi][ni][3]);
            }
        }
    }
}

// ============================================================================
// launch
// ============================================================================
extern "C" void kernel_launch(void* const* d_in, const int* in_sizes, int n_in,
                              void* d_out, int out_size) {
    const float* A  = (const float*)d_in[0];   // (64, 64) diagonal
    const float* Bm = (const float*)d_in[1];   // (64, 128)
    const float* C  = (const float*)d_in[2];   // (128, 64)
    float* out = (float*)d_out;                // (4096, 128, 128) fp32

    s4d_prep_vf<<<VF_ELEMS / 256, 256>>>(A);
    s4d_prep_wf<<<WF_ELEMS / 256, 256>>>(C, Bm);

    dim3 grid(COLS_TOTAL / 256, L_LEN / 128);  // (64, 32) = 2048 CTAs
    s4d_mma_kernel<<<grid, 256>>>(out);
}

// round 6
// speedup vs baseline: 1.0519x; 1.0519x over previous
#include <cuda_runtime.h>
#include <cuda_bf16.h>
#include <cstdint>

// ============================================================================
// S4D: K[i] = C @ A^i @ B, A diagonal.
//   K[i][m][d] = sum_n C[m][n] * a_n^i * B[n][d]
//   => GEMM: K[4096, 16384] = V[4096, 64] @ W[64, 16384]
// sm_103 generic target -> mma.sync bf16 (HMMA), bf16x3 split
// (hi*hi + hi*lo + lo*hi), operands pre-stored in fragment order (no SMEM).
// R6: persistent CTAs (strip-major chunks -> A frags hit L1), interleaved
// W hi/lo (LDG.128), streaming stores, merged prep.
// ============================================================================

#define L_LEN 4096
#define NS 64
#define DM 128
#define COLS_TOTAL (DM * DM)   // 16384

#define N_TILES 4096           // 32 strips x 128 col-tiles (128x128 each)
#define N_CTAS 304             // 2 per SM on GB300 (152 SMs)
#define CHUNK 14               // ceil(4096/304)

// A-fragment arrays: [blkf(256)][ks(4)][lane(32)] uint4; r0 = blkf*16 + lane/4
#define VF_ELEMS (256 * 4 * 32)          // 32768
// B-fragment array (hi/lo interleaved): [nbf(2048)][ks(4)][lane(32)] uint4
//   .x .y = bhi b0,b1 ; .z .w = blo b0,b1 ; col = nbf*8 + lane/4
#define WF_ELEMS (2048 * 4 * 32)         // 262144

__device__ uint4 g_VFhi[VF_ELEMS];
__device__ uint4 g_VFlo[VF_ELEMS];
__device__ uint4 g_WF[WF_ELEMS];
__device__ double g_l2a[NS];

__device__ __forceinline__ void mma_16816(float* c, const uint32_t* a,
                                          const uint32_t* b) {
    asm volatile(
        "mma.sync.aligned.m16n8k16.row.col.f32.bf16.bf16.f32 "
        "{%0,%1,%2,%3}, {%4,%5,%6,%7}, {%8,%9}, {%0,%1,%2,%3};"
        : "+f"(c[0]), "+f"(c[1]), "+f"(c[2]), "+f"(c[3])
        : "r"(a[0]), "r"(a[1]), "r"(a[2]), "r"(a[3]), "r"(b[0]), "r"(b[1]));
}

__device__ __forceinline__ uint32_t pack_bf2(__nv_bfloat16 x, __nv_bfloat16 y) {
    __nv_bfloat162 t(x, y);
    return *(uint32_t*)&t;
}

__device__ __forceinline__ void split2(float v0, float v1,
                                       uint32_t& hi, uint32_t& lo) {
    __nv_bfloat16 h0 = __float2bfloat16(v0);
    __nv_bfloat16 h1 = __float2bfloat16(v1);
    float l0 = v0 - __bfloat162float(h0);
    float l1 = v1 - __bfloat162float(h1);
    hi = pack_bf2(h0, h1);
    lo = pack_bf2(__float2bfloat16(l0), __float2bfloat16(l1));
}

// v(i,n) = a_n^i = 2^(i*l2a) : one fp64 mul + exp2f + ldexpf
__device__ __forceinline__ float pow_in(int i, double l2) {
    double e = (double)i * l2;
    if (e < -200.0) return 0.0f;
    double fl = floor(e);
    return ldexpf(exp2f((float)(e - fl)), (int)fl);
}

// ============================================================================
// Prep 0: fp64 log2 of the diagonal, once (64 threads).
// ============================================================================
__global__ void s4d_prep_log(const float* __restrict__ A) {
    int n = threadIdx.x;
    if (n < NS) {
        float a = A[n * NS + n];
        g_l2a[n] = (a > 0.0f) ? log2((double)a) : -1.0e30;
    }
}

// ============================================================================
// Merged prep: blocks [0,128) build V fragments, [128,1152) build W fragments.
// ============================================================================
#define VF_BLOCKS (VF_ELEMS / 256)       // 128
#define WF_BLOCKS (WF_ELEMS / 256)       // 1024

__global__ void s4d_prep_frag(const float* __restrict__ C,
                              const float* __restrict__ Bm) {
    if (blockIdx.x < VF_BLOCKS) {
        int idx = blockIdx.x * 256 + threadIdx.x;
        int lane = idx & 31;
        int ks   = (idx >> 5) & 3;
        int blkf = idx >> 7;
        int g  = lane >> 2;
        int tg = lane & 3;
        int r0 = blkf * 16 + g;
        int r1 = r0 + 8;
        int k0 = ks * 16 + tg * 2;

        double l2_0 = g_l2a[k0],     l2_1 = g_l2a[k0 + 1];
        double l2_8 = g_l2a[k0 + 8], l2_9 = g_l2a[k0 + 9];

        uint4 hi, lo;
        split2(pow_in(r0, l2_0), pow_in(r0, l2_1), hi.x, lo.x);
        split2(pow_in(r1, l2_0), pow_in(r1, l2_1), hi.y, lo.y);
        split2(pow_in(r0, l2_8), pow_in(r0, l2_9), hi.z, lo.z);
        split2(pow_in(r1, l2_8), pow_in(r1, l2_9), hi.w, lo.w);
        g_VFhi[idx] = hi;
        g_VFlo[idx] = lo;
    } else {
        int idx = (blockIdx.x - VF_BLOCKS) * 256 + threadIdx.x;
        int lane = idx & 31;
        int ks   = (idx >> 5) & 3;
        int nbf  = idx >> 7;
        int g  = lane >> 2;
        int tg = lane & 3;
        int col = nbf * 8 + g;
        int k0  = ks * 16 + tg * 2;
        int m = col >> 7;
        int d = col & 127;

        const float* Crow = C + m * NS;
        float w0 = Crow[k0]     * Bm[k0 * DM + d];
        float w1 = Crow[k0 + 1] * Bm[(k0 + 1) * DM + d];
        float w8 = Crow[k0 + 8] * Bm[(k0 + 8) * DM + d];
        float w9 = Crow[k0 + 9] * Bm[(k0 + 9) * DM + d];

        uint4 w;                          // .xy = hi(b0,b1), .zw = lo(b0,b1)
        split2(w0, w1, w.x, w.z);
        split2(w8, w9, w.y, w.w);
        g_WF[idx] = w;
    }
}

// ============================================================================
// Main: persistent CTAs. Each CTA processes CHUNK consecutive col-tiles in
// one row-strip (A fragments L1-resident after the first tile).
// Tile = 128(i) x 128(col), 8 warps of 64x32. Fragment-order LDG, no SMEM.
// Per k-step: Ahi*(Bhi,Blo) then Alo*Bhi. Streaming stores.
// ============================================================================
__global__ void __launch_bounds__(256, 2) s4d_mma_kernel(float* __restrict__ out) {
    const int tid  = threadIdx.x;
    const int wid  = tid >> 5;
    const int lane = tid & 31;
    const int m_w = (wid & 1) * 64;
    const int n_w = (wid >> 1) * 32;

    for (int j = 0; j < CHUNK; j++) {
        const int t = blockIdx.x * CHUNK + j;
        if (t >= N_TILES) return;
        const int bx = t & 127;           // col-tile (fast within a strip)
        const int by = t >> 7;            // row-strip

        // A base: ((by*8 + m_w/16 + mi)*4 + ks)*32 + lane
        const int abase = (by * 8 + (m_w >> 4)) * 128 + lane;
        // B base: ((bx*16 + n_w/8 + ni)*4 + ks)*32 + lane
        const int bbase = (bx * 16 + (n_w >> 3)) * 128 + lane;

        float c[4][4][4];
#pragma unroll
        for (int mi = 0; mi < 4; mi++)
#pragma unroll
            for (int ni = 0; ni < 4; ni++)
#pragma unroll
                for (int k = 0; k < 4; k++) c[mi][ni][k] = 0.0f;

#pragma unroll
        for (int ks = 0; ks < 4; ks++) {
            uint4 ahi[4];
            uint4 bw[4];
#pragma unroll
            for (int mi = 0; mi < 4; mi++)
                ahi[mi] = g_VFhi[abase + mi * 128 + ks * 32];
#pragma unroll
            for (int ni = 0; ni < 4; ni++)
                bw[ni] = g_WF[bbase + ni * 128 + ks * 32];

#pragma unroll
            for (int mi = 0; mi < 4; mi++)
#pragma unroll
                for (int ni = 0; ni < 4; ni++)
                    mma_16816(c[mi][ni], (const uint32_t*)&ahi[mi],
                              (const uint32_t*)&bw[ni].x);     // B hi
#pragma unroll
            for (int mi = 0; mi < 4; mi++)
#pragma unroll
                for (int ni = 0; ni < 4; ni++)
                    mma_16816(c[mi][ni], (const uint32_t*)&ahi[mi],
                              (const uint32_t*)&bw[ni].z);     // B lo

            uint4 alo[4];
#pragma unroll
            for (int mi = 0; mi < 4; mi++)
                alo[mi] = g_VFlo[abase + mi * 128 + ks * 32];
#pragma unroll
            for (int mi = 0; mi < 4; mi++)
#pragma unroll
                for (int ni = 0; ni < 4; ni++)
                    mma_16816(c[mi][ni], (const uint32_t*)&alo[mi],
                              (const uint32_t*)&bw[ni].x);     // B hi
        }

        // epilogue: fragment-direct streaming float2 stores
        const int gm = by * 128 + m_w + (lane >> 2);
        const int gn = bx * 128 + n_w + (lane & 3) * 2;
#pragma unroll
        for (int mi = 0; mi < 4; mi++) {
            size_t r0 = (size_t)(gm + mi * 16) * COLS_TOTAL + gn;
            size_t r1 = r0 + (size_t)8 * COLS_TOTAL;
#pragma unroll
            for (int ni = 0; ni < 4; ni++) {
                __stcs((float2*)(out + r0 + ni * 8),
                       make_float2(c[mi][ni][0], c[mi][ni][1]));
                __stcs((float2*)(out + r1 + ni * 8),
                       make_float2(c[mi][ni][2], c[mi][ni][3]));
            }
        }
    }
}

// ============================================================================
// launch
// ============================================================================
extern "C" void kernel_launch(void* const* d_in, const int* in_sizes, int n_in,
                              void* d_out, int out_size) {
    const float* A  = (const float*)d_in[0];   // (64, 64) diagonal
    const float* Bm = (const float*)d_in[1];   // (64, 128)
    const float* C  = (const float*)d_in[2];   // (128, 64)
    float* out = (float*)d_out;                // (4096, 128, 128) fp32

    s4d_prep_log<<<1, 64>>>(A);
    s4d_prep_frag<<<VF_BLOCKS + WF_BLOCKS, 256>>>(C, Bm);
    s4d_mma_kernel<<<N_CTAS, 256>>>(out);
}